// round 10
// baseline (speedup 1.0000x reference)
#include <cuda_runtime.h>

#define NB 26
#define POSE_F 78        // 26*3 floats per pose
#define PPB 64           // poses per block (== TPB, thread t owns pose t)
#define TPB 64
#define BSTRIDE 39       // smem floats per pose (odd -> conflict-free compute)

#define TAB_F (NB * 5 + NB * 3)   // 130 rr5 entries + 78 rel_loc = 208

__device__ float g_tab[TAB_F];
__constant__ float c_tab[TAB_F];

#define C_RR5(i) c_tab[(i)]
#define C_RL(i)  c_tab[NB * 5 + (i)]

struct M3 { float a[9]; };
struct V3 { float v[3]; };

__device__ __forceinline__ float fsqrt_approx(float t) {
    t = fmaxf(t, 1e-30f);
    return t * rsqrtf(t);
}

// Core math shared by all step variants. Consumes angles, produces abs_loc + new state.
__device__ __forceinline__ void bone_math(int bone,
                                          const M3& Ap, const V3& bp,
                                          float ez, float ey, float ex,
                                          float& ax, float& ay, float& az,
                                          M3& Ao, V3& bo)
{
    const float lx = C_RL(bone * 3 + 0);
    const float ly = C_RL(bone * 3 + 1);
    const float lz = C_RL(bone * 3 + 2);

    ax = lx * Ap.a[0] + ly * Ap.a[3] + lz * Ap.a[6] + bp.v[0];
    ay = lx * Ap.a[1] + ly * Ap.a[4] + lz * Ap.a[7] + bp.v[1];
    az = lx * Ap.a[2] + ly * Ap.a[5] + lz * Ap.a[8] + bp.v[2];

    float sz, cz, sy, cy, sx, cx;
    __sincosf(ez, &sz, &cz);
    __sincosf(ey, &sy, &cy);
    __sincosf(ex, &sx, &cx);

    float M00 = C_RR5(bone * 5 + 0) * (cz * cy);
    float M10 = C_RR5(bone * 5 + 1) * (sz * cy);
    float M20 = C_RR5(bone * 5 + 2) * (-sy);
    float M21 = C_RR5(bone * 5 + 3) * (cy * sx);
    float M22 = C_RR5(bone * 5 + 4) * (cy * cx);

    float i0 = rsqrtf(fmaxf(M00 * M00 + M10 * M10, 1e-30f));
    float CZ = M00 * i0, SZ = M10 * i0;
    float SY = -M20;
    float CY = fsqrt_approx(1.0f - SY * SY);
    float i2 = rsqrtf(fmaxf(M21 * M21 + M22 * M22, 1e-30f));
    float CX = M22 * i2, SX = M21 * i2;

    float R00 = CZ * CY;
    float R01 = CZ * SY * SX - SZ * CX;
    float R02 = CZ * SY * CX + SZ * SX;
    float R10 = SZ * CY;
    float R11 = SZ * SY * SX + CZ * CX;
    float R12 = SZ * SY * CX - CZ * SX;
    float R20 = -SY;
    float R21 = CY * SX;
    float R22 = CY * CX;

    M3 T;
    #pragma unroll
    for (int k = 0; k < 3; k++) {
        float a0 = Ap.a[3 * k + 0], a1 = Ap.a[3 * k + 1], a2 = Ap.a[3 * k + 2];
        T.a[3 * k + 0] = a0 * R00 + a1 * R10 + a2 * R20;
        T.a[3 * k + 1] = a0 * R01 + a1 * R11 + a2 * R21;
        T.a[3 * k + 2] = a0 * R02 + a1 * R12 + a2 * R22;
    }
    float tx = bp.v[0] + lx, ty = bp.v[1] + ly, tz = bp.v[2] + lz;
    V3 tb;
    tb.v[0] = tx * R00 + ty * R10 + tz * R20;
    tb.v[1] = tx * R01 + ty * R11 + tz * R21;
    tb.v[2] = tx * R02 + ty * R12 + tz * R22;
    Ao = T;
    bo = tb;
}

// Full step reading/writing shared buffer at float offset (3*bone + off).
__device__ __forceinline__ void fullstep(int bone, int off, M3 Ap, V3 bp,
                                         M3& Ao, V3& bo, float* __restrict__ P)
{
    const int o = bone * 3 + off;
    float ez = P[o + 0], ey = P[o + 1], ex = P[o + 2];
    float ax, ay, az;
    bone_math(bone, Ap, bp, ez, ey, ex, ax, ay, az, Ao, bo);
    P[o + 0] = ax; P[o + 1] = ay; P[o + 2] = az;
}

__device__ __forceinline__ void leafstep(int bone, int off, const M3& Ap, const V3& bp,
                                         float* __restrict__ P)
{
    const float lx = C_RL(bone * 3 + 0);
    const float ly = C_RL(bone * 3 + 1);
    const float lz = C_RL(bone * 3 + 2);
    const int o = bone * 3 + off;
    P[o + 0] = lx * Ap.a[0] + ly * Ap.a[3] + lz * Ap.a[6] + bp.v[0];
    P[o + 1] = lx * Ap.a[1] + ly * Ap.a[4] + lz * Ap.a[7] + bp.v[1];
    P[o + 2] = lx * Ap.a[2] + ly * Ap.a[5] + lz * Ap.a[8] + bp.v[2];
}

__global__ void ref_table_kernel(const float* __restrict__ rel_rot_ref,
                                 const float* __restrict__ rel_loc)
{
    int i = threadIdx.x;
    if (i < NB) {
        float ez = rel_rot_ref[i * 3 + 0];
        float ey = rel_rot_ref[i * 3 + 1];
        float ex = rel_rot_ref[i * 3 + 2];
        float sz, cz, sy, cy, sx, cx;
        sincosf(ez, &sz, &cz);
        sincosf(ey, &sy, &cy);
        sincosf(ex, &sx, &cx);
        g_tab[i * 5 + 0] = cz * cy;
        g_tab[i * 5 + 1] = sz * cy;
        g_tab[i * 5 + 2] = -sy;
        g_tab[i * 5 + 3] = cy * sx;
        g_tab[i * 5 + 4] = cy * cx;
    }
    for (int j = i; j < NB * 3; j += blockDim.x)
        g_tab[NB * 5 + j] = rel_loc[j];
}

__global__ void __launch_bounds__(TPB, 14)
fk_kernel(const float* __restrict__ x,
          float* __restrict__ out)
{
    // buf: 39 floats per pose (seg1 = floats 0..38, later seg2 = floats 40..77 in slots 0..37)
    __shared__ float buf[PPB * BSTRIDE];     // 9984 B
    // carry: k-major, conflict-free. k 0-5 = A1 rows0,1; 6-8 = b1; 9-14 = A6 rows0,1; 15-17 = b6
    __shared__ float st[18 * PPB];           // 4608 B
    __shared__ float z13[PPB];               // bone 13 ez (float 39)          256 B

    const int tid = threadIdx.x;
    const float2* x2 = reinterpret_cast<const float2*>(x);
    float2* o2 = reinterpret_cast<float2*>(out);
    const size_t base2 = (size_t)blockIdx.x * (PPB * 39);  // float2 units

    // ---- stage seg1: floats [0,40) per pose = 20 float2. 64*20/64 = 20 iters exact.
    #pragma unroll
    for (int i = 0; i < 20; i++) {
        int s = i * TPB + tid;
        int p = s / 20, j = s % 20;
        float2 v = x2[base2 + p * 39 + j];
        if (j < 19) {
            buf[p * BSTRIDE + 2 * j]     = v.x;
            buf[p * BSTRIDE + 2 * j + 1] = v.y;
        } else {
            buf[p * BSTRIDE + 38] = v.x;   // float 38 (bone12 ex input)
            z13[p] = v.y;                  // float 39 = bone13 ez
        }
    }
    __syncthreads();

    float* P = buf + tid * BSTRIDE;
    float ez13 = z13[tid];                 // own-pose, safe after sync

    M3 A, Asv; V3 b, bsv;

    // ---- seg1 compute: bones 0..12 ----
    {
        M3 I; V3 z;
        I.a[0]=1.f; I.a[1]=0.f; I.a[2]=0.f;
        I.a[3]=0.f; I.a[4]=1.f; I.a[5]=0.f;
        I.a[6]=0.f; I.a[7]=0.f; I.a[8]=1.f;
        z.v[0]=0.f; z.v[1]=0.f; z.v[2]=0.f;
        fullstep(0, 0, I, z, A, b, P);
    }
    fullstep(1, 0, A, b, A, b, P);
    // publish A1 (rows 0,1) + b1
    #pragma unroll
    for (int k = 0; k < 6; k++) st[k * PPB + tid] = A.a[k];
    #pragma unroll
    for (int k = 0; k < 3; k++) st[(6 + k) * PPB + tid] = b.v[k];

    fullstep(2, 0, A, b, A, b, P);
    fullstep(3, 0, A, b, A, b, P);
    fullstep(4, 0, A, b, Asv, bsv, P);     // Asv = A4 (register carry within seg1)
    fullstep(5, 0, Asv, bsv, A, b, P);
    fullstep(6, 0, A, b, A, b, P);
    // publish A6 (rows 0,1) + b6
    #pragma unroll
    for (int k = 0; k < 6; k++) st[(9 + k) * PPB + tid] = A.a[k];
    #pragma unroll
    for (int k = 0; k < 3; k++) st[(15 + k) * PPB + tid] = b.v[k];

    fullstep(7, 0, Asv, bsv, A, b, P);
    fullstep(8, 0, A, b, A, b, P);
    fullstep(9, 0, A, b, A, b, P);
    leafstep(10, 0, A, b, P);
    fullstep(11, 0, Asv, bsv, A, b, P);
    fullstep(12, 0, A, b, A, b, P);        // A = A12 carried in regs across phases

    __syncthreads();   // *** all poses' seg1 results complete before cross-pose reads ***

    // ---- write back seg1 results: floats [0,38) as 19 float2 + scalar float 38 ----
    #pragma unroll
    for (int i = 0; i < 19; i++) {
        int s = i * TPB + tid;
        int p = s / 19, j = s % 19;
        float2 v;
        v.x = buf[p * BSTRIDE + 2 * j];
        v.y = buf[p * BSTRIDE + 2 * j + 1];
        o2[base2 + p * 39 + j] = v;
    }
    out[(size_t)blockIdx.x * (PPB * POSE_F) + tid * POSE_F + 38] = P[38];
    __syncthreads();   // all seg1 reads done before buffer reuse

    // ---- stage seg2: floats [40,78) per pose = 19 float2 into slots 0..37 ----
    #pragma unroll
    for (int i = 0; i < 19; i++) {
        int s = i * TPB + tid;
        int p = s / 19, j = s % 19;
        float2 v = x2[base2 + p * 39 + 20 + j];
        buf[p * BSTRIDE + 2 * j]     = v.x;
        buf[p * BSTRIDE + 2 * j + 1] = v.y;
    }
    __syncthreads();

    // ---- seg2 compute: bones 13..25 (buffer slot = float_index - 40) ----
    // bone 13: ez from reg, ey/ex at slots 0,1; abs: ax->reg, ay/az->slots 0,1
    float axb13;
    {
        float ey = P[0], ex = P[1];
        float ax, ay, az;
        bone_math(13, A, b, ez13, ey, ex, ax, ay, az, A, b);
        axb13 = ax; P[0] = ay; P[1] = az;
    }
    leafstep(14, -40, A, b, P);

    // chains off A1 (reload + reconstruct row2 = r0 x r1)
    M3 C; V3 cb;
    #pragma unroll
    for (int k = 0; k < 6; k++) C.a[k] = st[k * PPB + tid];
    #pragma unroll
    for (int k = 0; k < 3; k++) cb.v[k] = st[(6 + k) * PPB + tid];
    C.a[6] = C.a[1] * C.a[5] - C.a[2] * C.a[4];
    C.a[7] = C.a[2] * C.a[3] - C.a[0] * C.a[5];
    C.a[8] = C.a[0] * C.a[4] - C.a[1] * C.a[3];

    fullstep(15, -40, C, cb, A, b, P);
    fullstep(16, -40, A, b, A, b, P);
    fullstep(17, -40, A, b, A, b, P);
    leafstep(18, -40, A, b, P);
    fullstep(19, -40, C, cb, A, b, P);
    fullstep(20, -40, A, b, A, b, P);
    fullstep(21, -40, A, b, A, b, P);
    leafstep(22, -40, A, b, P);

    // head leaves off A6
    #pragma unroll
    for (int k = 0; k < 6; k++) C.a[k] = st[(9 + k) * PPB + tid];
    #pragma unroll
    for (int k = 0; k < 3; k++) cb.v[k] = st[(15 + k) * PPB + tid];
    C.a[6] = C.a[1] * C.a[5] - C.a[2] * C.a[4];
    C.a[7] = C.a[2] * C.a[3] - C.a[0] * C.a[5];
    C.a[8] = C.a[0] * C.a[4] - C.a[1] * C.a[3];
    leafstep(23, -40, C, cb, P);
    leafstep(24, -40, C, cb, P);
    leafstep(25, -40, C, cb, P);

    __syncthreads();   // all poses' seg2 results complete before cross-pose reads

    // ---- write back seg2: floats [40,78) as 19 float2 + scalar float 39 (bone13 ax) ----
    #pragma unroll
    for (int i = 0; i < 19; i++) {
        int s = i * TPB + tid;
        int p = s / 19, j = s % 19;
        float2 v;
        v.x = buf[p * BSTRIDE + 2 * j];
        v.y = buf[p * BSTRIDE + 2 * j + 1];
        o2[base2 + p * 39 + 20 + j] = v;
    }
    out[(size_t)blockIdx.x * (PPB * POSE_F) + tid * POSE_F + 39] = axb13;
}

extern "C" void kernel_launch(void* const* d_in, const int* in_sizes, int n_in,
                              void* d_out, int out_size)
{
    const float* x           = (const float*)d_in[0];  // (131072, 26, 3)
    const float* rel_loc     = (const float*)d_in[1];  // (26, 3)
    const float* rel_rot_ref = (const float*)d_in[2];  // (26, 3)
    float* out               = (float*)d_out;          // (131072, 26, 3)

    const int batch = in_sizes[0] / POSE_F;            // 131072

    ref_table_kernel<<<1, 128>>>(rel_rot_ref, rel_loc);

    void* g_tab_ptr = nullptr;
    cudaGetSymbolAddress(&g_tab_ptr, g_tab);
    cudaMemcpyToSymbolAsync(c_tab, g_tab_ptr, sizeof(float) * TAB_F, 0,
                            cudaMemcpyDeviceToDevice, 0);

    fk_kernel<<<batch / PPB, TPB>>>(x, out);
}

// round 12
// speedup vs baseline: 1.8843x; 1.8843x over previous
#include <cuda_runtime.h>

#define NB 26
#define POSE_F 78        // 26*3 floats per pose
#define TPB 64
#define BATCH 131072

#define TAB_F (NB * 5 + NB * 3)   // 130 rr5 entries + 78 rel_loc = 208

__device__ float g_tab[TAB_F];
__constant__ float c_tab[TAB_F];

#define C_RR5(i) c_tab[(i)]
#define C_RL(i)  c_tab[NB * 5 + (i)]

struct M3 { float a[9]; };
struct V3 { float v[3]; };

__device__ __forceinline__ float fsqrt_approx(float t) {
    t = fmaxf(t, 1e-30f);
    return t * rsqrtf(t);
}

// Full bone step. Ap/bp by CONST REF, Ao/bo DISTINCT outputs (no aliasing at any
// call site) -> no defensive copy, no temp matrix: results written straight to Ao.
__device__ __forceinline__ void fullstep(int bone, const M3& Ap, const V3& bp,
                                         M3& Ao, V3& bo, float* __restrict__ P)
{
    const float lx = C_RL(bone * 3 + 0);
    const float ly = C_RL(bone * 3 + 1);
    const float lz = C_RL(bone * 3 + 2);

    // abs_loc[bone] = l . Ap + bp
    float ax = lx * Ap.a[0] + ly * Ap.a[3] + lz * Ap.a[6] + bp.v[0];
    float ay = lx * Ap.a[1] + ly * Ap.a[4] + lz * Ap.a[7] + bp.v[1];
    float az = lx * Ap.a[2] + ly * Ap.a[5] + lz * Ap.a[8] + bp.v[2];

    float ez = P[bone * 3 + 0];
    float ey = P[bone * 3 + 1];
    float ex = P[bone * 3 + 2];
    P[bone * 3 + 0] = ax;
    P[bone * 3 + 1] = ay;
    P[bone * 3 + 2] = az;

    float sz, cz, sy, cy, sx, cx;
    __sincosf(ez, &sz, &cz);
    __sincosf(ey, &sy, &cy);
    __sincosf(ex, &sx, &cx);

    // 5 needed entries of M = R_ref (hadamard) R_chg
    float M00 = C_RR5(bone * 5 + 0) * (cz * cy);
    float M10 = C_RR5(bone * 5 + 1) * (sz * cy);
    float M20 = C_RR5(bone * 5 + 2) * (-sy);
    float M21 = C_RR5(bone * 5 + 3) * (cy * sx);
    float M22 = C_RR5(bone * 5 + 4) * (cy * cx);

    // Trig-free euler->matrix rebuild
    float i0 = rsqrtf(fmaxf(M00 * M00 + M10 * M10, 1e-30f));
    float CZ = M00 * i0, SZ = M10 * i0;
    float SY = -M20;
    float CY = fsqrt_approx(1.0f - SY * SY);
    float i2 = rsqrtf(fmaxf(M21 * M21 + M22 * M22, 1e-30f));
    float CX = M22 * i2, SX = M21 * i2;

    float R00 = CZ * CY;
    float R01 = CZ * SY * SX - SZ * CX;
    float R02 = CZ * SY * CX + SZ * SX;
    float R10 = SZ * CY;
    float R11 = SZ * SY * SX + CZ * CX;
    float R12 = SZ * SY * CX - CZ * SX;
    float R20 = -SY;
    float R21 = CY * SX;
    float R22 = CY * CX;

    // Ao = Ap @ R  (direct write, Ao != Ap guaranteed)
    #pragma unroll
    for (int k = 0; k < 3; k++) {
        float a0 = Ap.a[3 * k + 0], a1 = Ap.a[3 * k + 1], a2 = Ap.a[3 * k + 2];
        Ao.a[3 * k + 0] = a0 * R00 + a1 * R10 + a2 * R20;
        Ao.a[3 * k + 1] = a0 * R01 + a1 * R11 + a2 * R21;
        Ao.a[3 * k + 2] = a0 * R02 + a1 * R12 + a2 * R22;
    }
    float tx = bp.v[0] + lx, ty = bp.v[1] + ly, tz = bp.v[2] + lz;
    bo.v[0] = tx * R00 + ty * R10 + tz * R20;
    bo.v[1] = tx * R01 + ty * R11 + tz * R21;
    bo.v[2] = tx * R02 + ty * R12 + tz * R22;
}

__device__ __forceinline__ void leafstep(int bone, const M3& Ap, const V3& bp,
                                         float* __restrict__ P)
{
    const float lx = C_RL(bone * 3 + 0);
    const float ly = C_RL(bone * 3 + 1);
    const float lz = C_RL(bone * 3 + 2);
    P[bone * 3 + 0] = lx * Ap.a[0] + ly * Ap.a[3] + lz * Ap.a[6] + bp.v[0];
    P[bone * 3 + 1] = lx * Ap.a[1] + ly * Ap.a[4] + lz * Ap.a[7] + bp.v[1];
    P[bone * 3 + 2] = lx * Ap.a[2] + ly * Ap.a[5] + lz * Ap.a[8] + bp.v[2];
}

__global__ void ref_table_kernel(const float* __restrict__ rel_rot_ref,
                                 const float* __restrict__ rel_loc)
{
    int i = threadIdx.x;
    if (i < NB) {
        float ez = rel_rot_ref[i * 3 + 0];
        float ey = rel_rot_ref[i * 3 + 1];
        float ex = rel_rot_ref[i * 3 + 2];
        float sz, cz, sy, cy, sx, cx;
        sincosf(ez, &sz, &cz);
        sincosf(ey, &sy, &cy);
        sincosf(ex, &sx, &cx);
        g_tab[i * 5 + 0] = cz * cy;
        g_tab[i * 5 + 1] = sz * cy;
        g_tab[i * 5 + 2] = -sy;
        g_tab[i * 5 + 3] = cy * sx;
        g_tab[i * 5 + 4] = cy * cx;
    }
    for (int j = i; j < NB * 3; j += blockDim.x)
        g_tab[NB * 5 + j] = rel_loc[j];
}

__global__ void __launch_bounds__(TPB, 11)
fk_kernel(const float* __restrict__ x,
          float* __restrict__ out)
{
    __shared__ float pose[TPB * POSE_F];

    const int tid = threadIdx.x;

    const int NV4 = TPB * POSE_F / 4;                 // 1248
    const int NIT = (NV4 + TPB - 1) / TPB;            // 20
    const float4* gin = reinterpret_cast<const float4*>(x) + (size_t)blockIdx.x * NV4;
    float4* sp4 = reinterpret_cast<float4*>(pose);
    #pragma unroll
    for (int i = 0; i < NIT; i++) {
        int idx = tid + i * TPB;
        if (idx < NV4) sp4[idx] = gin[idx];
    }
    __syncthreads();

    float* P = pose + tid * POSE_F;

    // Four ping-pong state slots; every fullstep has distinct in/out.
    M3 S, T, U, V;
    V3 sb, tb, ub, vb;

    // root
    {
        M3 I; V3 z;
        I.a[0]=1.f; I.a[1]=0.f; I.a[2]=0.f;
        I.a[3]=0.f; I.a[4]=1.f; I.a[5]=0.f;
        I.a[6]=0.f; I.a[7]=0.f; I.a[8]=1.f;
        z.v[0]=0.f; z.v[1]=0.f; z.v[2]=0.f;
        fullstep(0, I, z, S, sb, P);          // S = A0
    }
    fullstep(1, S, sb, T, tb, P);             // T = A1 (feeds 15, 19, 2)

    fullstep(15, T, tb, U, ub, P);            // U = chain-a
    fullstep(19, T, tb, V, vb, P);            // V = chain-b
    fullstep(2,  T, tb, S, sb, P);            // S = A2        (T free)

    fullstep(16, U, ub, T, tb, P);            // T = chain-a   (U free)
    fullstep(20, V, vb, U, ub, P);            // U = chain-b   (V free)
    fullstep(3,  S, sb, V, vb, P);            // V = A3        (S free)

    fullstep(17, T, tb, S, sb, P);            // S = chain-a   (T free)
    fullstep(21, U, ub, T, tb, P);            // T = chain-b   (U free)
    fullstep(4,  V, vb, U, ub, P);            // U = A4 (feeds 7, 11, 5)  (V free)

    leafstep(18, S, sb, P);                   // (S free)
    leafstep(22, T, tb, P);                   // (T free)

    fullstep(7,  U, ub, S, sb, P);            // S = chain-a
    fullstep(11, U, ub, T, tb, P);            // T = chain-b
    fullstep(5,  U, ub, V, vb, P);            // V = A5        (U free)

    fullstep(8,  S, sb, U, ub, P);            // U = chain-a   (S free)
    fullstep(12, T, tb, S, sb, P);            // S = chain-b   (T free)
    fullstep(6,  V, vb, T, tb, P);            // T = A6 (head) (V free)

    fullstep(9,  U, ub, V, vb, P);            // V = chain-a   (U free)
    fullstep(13, S, sb, U, ub, P);            // U = chain-b   (S free)

    leafstep(10, V, vb, P);
    leafstep(14, U, ub, P);
    leafstep(23, T, tb, P);
    leafstep(24, T, tb, P);
    leafstep(25, T, tb, P);

    __syncthreads();

    float4* gout = reinterpret_cast<float4*>(out) + (size_t)blockIdx.x * NV4;
    #pragma unroll
    for (int i = 0; i < NIT; i++) {
        int idx = tid + i * TPB;
        if (idx < NV4) gout[idx] = sp4[idx];
    }
}

extern "C" void kernel_launch(void* const* d_in, const int* in_sizes, int n_in,
                              void* d_out, int out_size)
{
    const float* x           = (const float*)d_in[0];  // (131072, 26, 3)
    const float* rel_loc     = (const float*)d_in[1];  // (26, 3)
    const float* rel_rot_ref = (const float*)d_in[2];  // (26, 3)
    float* out               = (float*)d_out;          // (131072, 26, 3)

    const int batch = in_sizes[0] / POSE_F;            // 131072

    ref_table_kernel<<<1, 128>>>(rel_rot_ref, rel_loc);

    void* g_tab_ptr = nullptr;
    cudaGetSymbolAddress(&g_tab_ptr, g_tab);
    cudaMemcpyToSymbolAsync(c_tab, g_tab_ptr, sizeof(float) * TAB_F, 0,
                            cudaMemcpyDeviceToDevice, 0);

    fk_kernel<<<batch / TPB, TPB>>>(x, out);
}

// round 13
// speedup vs baseline: 1.9959x; 1.0592x over previous
#include <cuda_runtime.h>

#define NB 26
#define POSE_F 78        // 26*3 floats per pose
#define TPB 64
#define BATCH 131072

#define TAB_F (NB * 5 + NB * 3)   // 130 rr5 entries + 78 rel_loc = 208

__device__ float g_tab[TAB_F];
__constant__ float c_tab[TAB_F];

#define C_RR5(i) c_tab[(i)]
#define C_RL(i)  c_tab[NB * 5 + (i)]

struct M3 { float a[9]; };
struct V3 { float v[3]; };

__device__ __forceinline__ float fsqrt_approx(float t) {
    t = fmaxf(t, 1e-30f);
    return t * rsqrtf(t);
}

// INDEPENDENT half: angles -> rebuilt rotation R. No chain dependency.
__device__ __forceinline__ void buildR(int bone, const float* __restrict__ P,
                                       float R[9])
{
    float ez = P[bone * 3 + 0];
    float ey = P[bone * 3 + 1];
    float ex = P[bone * 3 + 2];

    float sz, cz, sy, cy, sx, cx;
    __sincosf(ez, &sz, &cz);
    __sincosf(ey, &sy, &cy);
    __sincosf(ex, &sx, &cx);

    // 5 needed entries of M = R_ref (hadamard) R_chg
    float M00 = C_RR5(bone * 5 + 0) * (cz * cy);
    float M10 = C_RR5(bone * 5 + 1) * (sz * cy);
    float M20 = C_RR5(bone * 5 + 2) * (-sy);
    float M21 = C_RR5(bone * 5 + 3) * (cy * sx);
    float M22 = C_RR5(bone * 5 + 4) * (cy * cx);

    // Trig-free euler->matrix rebuild
    float i0 = rsqrtf(fmaxf(M00 * M00 + M10 * M10, 1e-30f));
    float CZ = M00 * i0, SZ = M10 * i0;
    float SY = -M20;
    float CY = fsqrt_approx(1.0f - SY * SY);
    float i2 = rsqrtf(fmaxf(M21 * M21 + M22 * M22, 1e-30f));
    float CX = M22 * i2, SX = M21 * i2;

    float czsy = CZ * SY, szsy = SZ * SY;
    R[0] = CZ * CY;
    R[1] = czsy * SX - SZ * CX;
    R[2] = czsy * CX + SZ * SX;
    R[3] = SZ * CY;
    R[4] = szsy * SX + CZ * CX;
    R[5] = szsy * CX - CZ * SX;
    R[6] = -SY;
    R[7] = CY * SX;
    R[8] = CY * CX;
}

// DEPENDENT half: abs_loc + A/b chain update using a prebuilt R.
// Ao/bo distinct from Ap/bp at every call site.
__device__ __forceinline__ void chain(int bone, const float R[9],
                                      const M3& Ap, const V3& bp,
                                      M3& Ao, V3& bo, float* __restrict__ P)
{
    const float lx = C_RL(bone * 3 + 0);
    const float ly = C_RL(bone * 3 + 1);
    const float lz = C_RL(bone * 3 + 2);

    P[bone * 3 + 0] = lx * Ap.a[0] + ly * Ap.a[3] + lz * Ap.a[6] + bp.v[0];
    P[bone * 3 + 1] = lx * Ap.a[1] + ly * Ap.a[4] + lz * Ap.a[7] + bp.v[1];
    P[bone * 3 + 2] = lx * Ap.a[2] + ly * Ap.a[5] + lz * Ap.a[8] + bp.v[2];

    #pragma unroll
    for (int k = 0; k < 3; k++) {
        float a0 = Ap.a[3 * k + 0], a1 = Ap.a[3 * k + 1], a2 = Ap.a[3 * k + 2];
        Ao.a[3 * k + 0] = a0 * R[0] + a1 * R[3] + a2 * R[6];
        Ao.a[3 * k + 1] = a0 * R[1] + a1 * R[4] + a2 * R[7];
        Ao.a[3 * k + 2] = a0 * R[2] + a1 * R[5] + a2 * R[8];
    }
    float tx = bp.v[0] + lx, ty = bp.v[1] + ly, tz = bp.v[2] + lz;
    bo.v[0] = tx * R[0] + ty * R[3] + tz * R[6];
    bo.v[1] = tx * R[1] + ty * R[4] + tz * R[7];
    bo.v[2] = tx * R[2] + ty * R[5] + tz * R[8];
}

__device__ __forceinline__ void leafstep(int bone, const M3& Ap, const V3& bp,
                                         float* __restrict__ P)
{
    const float lx = C_RL(bone * 3 + 0);
    const float ly = C_RL(bone * 3 + 1);
    const float lz = C_RL(bone * 3 + 2);
    P[bone * 3 + 0] = lx * Ap.a[0] + ly * Ap.a[3] + lz * Ap.a[6] + bp.v[0];
    P[bone * 3 + 1] = lx * Ap.a[1] + ly * Ap.a[4] + lz * Ap.a[7] + bp.v[1];
    P[bone * 3 + 2] = lx * Ap.a[2] + ly * Ap.a[5] + lz * Ap.a[8] + bp.v[2];
}

__global__ void ref_table_kernel(const float* __restrict__ rel_rot_ref,
                                 const float* __restrict__ rel_loc)
{
    int i = threadIdx.x;
    if (i < NB) {
        float ez = rel_rot_ref[i * 3 + 0];
        float ey = rel_rot_ref[i * 3 + 1];
        float ex = rel_rot_ref[i * 3 + 2];
        float sz, cz, sy, cy, sx, cx;
        sincosf(ez, &sz, &cz);
        sincosf(ey, &sy, &cy);
        sincosf(ex, &sx, &cx);
        g_tab[i * 5 + 0] = cz * cy;
        g_tab[i * 5 + 1] = sz * cy;
        g_tab[i * 5 + 2] = -sy;
        g_tab[i * 5 + 3] = cy * sx;
        g_tab[i * 5 + 4] = cy * cx;
    }
    for (int j = i; j < NB * 3; j += blockDim.x)
        g_tab[NB * 5 + j] = rel_loc[j];
}

__global__ void __launch_bounds__(TPB, 10)
fk_kernel(const float* __restrict__ x,
          float* __restrict__ out)
{
    __shared__ float pose[TPB * POSE_F];

    const int tid = threadIdx.x;

    const int NV4 = TPB * POSE_F / 4;                 // 1248
    const int NIT = (NV4 + TPB - 1) / TPB;            // 20
    const float4* gin = reinterpret_cast<const float4*>(x) + (size_t)blockIdx.x * NV4;
    float4* sp4 = reinterpret_cast<float4*>(pose);
    #pragma unroll
    for (int i = 0; i < NIT; i++) {
        int idx = tid + i * TPB;
        if (idx < NV4) sp4[idx] = gin[idx];
    }
    __syncthreads();

    float* P = pose + tid * POSE_F;

    M3 S, T, U, V;
    V3 sb, tb, ub, vb;
    float Ra[9], Rb[9];

    // Depth-2 software pipeline: buildR(next bone) interleaved with chain(current).
    // buildR is chain-independent -> guaranteed overlap work for the scheduler.
    {
        M3 I; V3 z;
        I.a[0]=1.f; I.a[1]=0.f; I.a[2]=0.f;
        I.a[3]=0.f; I.a[4]=1.f; I.a[5]=0.f;
        I.a[6]=0.f; I.a[7]=0.f; I.a[8]=1.f;
        z.v[0]=0.f; z.v[1]=0.f; z.v[2]=0.f;

        buildR(0, P, Ra);
        buildR(1, P, Rb);    chain(0,  Ra, I, z,  S, sb, P);   // S = A0
    }
    buildR(15, P, Ra);   chain(1,  Rb, S, sb, T, tb, P);       // T = A1
    buildR(19, P, Rb);   chain(15, Ra, T, tb, U, ub, P);       // U = chain-a
    buildR(2,  P, Ra);   chain(19, Rb, T, tb, V, vb, P);       // V = chain-b
    buildR(16, P, Rb);   chain(2,  Ra, T, tb, S, sb, P);       // S = A2
    buildR(20, P, Ra);   chain(16, Rb, U, ub, T, tb, P);       // T = chain-a
    buildR(3,  P, Rb);   chain(20, Ra, V, vb, U, ub, P);       // U = chain-b
    buildR(17, P, Ra);   chain(3,  Rb, S, sb, V, vb, P);       // V = A3
    buildR(21, P, Rb);   chain(17, Ra, T, tb, S, sb, P);       // S = chain-a
    buildR(4,  P, Ra);   chain(21, Rb, U, ub, T, tb, P);       // T = chain-b
    buildR(7,  P, Rb);   chain(4,  Ra, V, vb, U, ub, P);       // U = A4

    leafstep(18, S, sb, P);    // chain-a end
    leafstep(22, T, tb, P);    // chain-b end

    buildR(11, P, Ra);   chain(7,  Rb, U, ub, S, sb, P);       // S = chain-a
    buildR(5,  P, Rb);   chain(11, Ra, U, ub, T, tb, P);       // T = chain-b
    buildR(8,  P, Ra);   chain(5,  Rb, U, ub, V, vb, P);       // V = A5
    buildR(12, P, Rb);   chain(8,  Ra, S, sb, U, ub, P);       // U = chain-a
    buildR(6,  P, Ra);   chain(12, Rb, T, tb, S, sb, P);       // S = chain-b
    buildR(9,  P, Rb);   chain(6,  Ra, V, vb, T, tb, P);       // T = A6
    buildR(13, P, Ra);   chain(9,  Rb, U, ub, V, vb, P);       // V = chain-a
                         chain(13, Ra, S, sb, U, ub, P);       // U = chain-b

    leafstep(10, V, vb, P);
    leafstep(14, U, ub, P);
    leafstep(23, T, tb, P);
    leafstep(24, T, tb, P);
    leafstep(25, T, tb, P);

    __syncthreads();

    float4* gout = reinterpret_cast<float4*>(out) + (size_t)blockIdx.x * NV4;
    #pragma unroll
    for (int i = 0; i < NIT; i++) {
        int idx = tid + i * TPB;
        if (idx < NV4) gout[idx] = sp4[idx];
    }
}

extern "C" void kernel_launch(void* const* d_in, const int* in_sizes, int n_in,
                              void* d_out, int out_size)
{
    const float* x           = (const float*)d_in[0];  // (131072, 26, 3)
    const float* rel_loc     = (const float*)d_in[1];  // (26, 3)
    const float* rel_rot_ref = (const float*)d_in[2];  // (26, 3)
    float* out               = (float*)d_out;          // (131072, 26, 3)

    const int batch = in_sizes[0] / POSE_F;            // 131072

    ref_table_kernel<<<1, 128>>>(rel_rot_ref, rel_loc);

    void* g_tab_ptr = nullptr;
    cudaGetSymbolAddress(&g_tab_ptr, g_tab);
    cudaMemcpyToSymbolAsync(c_tab, g_tab_ptr, sizeof(float) * TAB_F, 0,
                            cudaMemcpyDeviceToDevice, 0);

    fk_kernel<<<batch / TPB, TPB>>>(x, out);
}